// round 3
// baseline (speedup 1.0000x reference)
#include <cuda_runtime.h>

#define NB 32
#define NC 256
#define NHW 3136
#define NHW4 784          // float4 per plane
#define NG 32
#define EPSV 1e-5f

#define TPB 224           // 7 warps; 2*784 / 224 = 7 exactly
#define PER_TH 7
#define NPAIR (NB * NC / 2)   // 4096 blocks, 2 planes each

__device__ float d_pooled[NB * NC];
__device__ float d_scale[NB * NC];
__device__ float d_shift[NB * NC];

// ---------------------------------------------------------------------------
// Pass 1: mean pool, 2 planes per block, 7 fully-unrolled float4 loads/thread.
// ---------------------------------------------------------------------------
__global__ __launch_bounds__(TPB) void pool_kernel(const float* __restrict__ x) {
    const int pair = blockIdx.x;
    const float4* __restrict__ xp =
        reinterpret_cast<const float4*>(x + (size_t)pair * 2 * NHW);

    // front-batched loads for MLP
    float4 v[PER_TH];
    #pragma unroll
    for (int k = 0; k < PER_TH; k++)
        v[k] = xp[threadIdx.x + k * TPB];

    float s0 = 0.0f, s1 = 0.0f;
    #pragma unroll
    for (int k = 0; k < PER_TH; k++) {
        const int j = threadIdx.x + k * TPB;
        const float t = (v[k].x + v[k].y) + (v[k].z + v[k].w);
        if (j < NHW4) s0 += t; else s1 += t;
    }

    __shared__ float sh0[8], sh1[8];
    const int lane = threadIdx.x & 31;
    const int wid  = threadIdx.x >> 5;
    #pragma unroll
    for (int o = 16; o > 0; o >>= 1) {
        s0 += __shfl_down_sync(0xffffffffu, s0, o);
        s1 += __shfl_down_sync(0xffffffffu, s1, o);
    }
    if (lane == 0) { sh0[wid] = s0; sh1[wid] = s1; }
    __syncthreads();
    if (threadIdx.x == 0) {
        float a = 0.0f, b = 0.0f;
        #pragma unroll
        for (int w = 0; w < 7; w++) { a += sh0[w]; b += sh1[w]; }
        d_pooled[pair * 2 + 0] = a * (1.0f / (float)NHW);
        d_pooled[pair * 2 + 1] = b * (1.0f / (float)NHW);
    }
}

// ---------------------------------------------------------------------------
// Pass 2: per-channel coefficients + per-batch alpha + fused scale/shift.
// Single block, 256 threads (thread == channel).
// ---------------------------------------------------------------------------
__global__ void coef_kernel(const float* __restrict__ alpha_w,
                            const float* __restrict__ alpha_b,
                            const float* __restrict__ g_w,
                            const float* __restrict__ g_b,
                            const float* __restrict__ g_rm,
                            const float* __restrict__ g_rv,
                            const float* __restrict__ grp_w,
                            const float* __restrict__ grp_b,
                            const float* __restrict__ grp_rm,
                            const float* __restrict__ grp_rv) {
    const int c = threadIdx.x;   // 0..255

    const float gs  = g_w[c] * rsqrtf(g_rv[c] + EPSV);
    const float gsh = g_b[c] - g_rm[c] * gs;

    float ms = 0.0f, msh = 0.0f;
    #pragma unroll 8
    for (int g = 0; g < NG; g++) {
        const int idx = g * NC + c;
        const float sg = grp_w[idx] * rsqrtf(grp_rv[idx] + EPSV);
        ms  += sg;
        msh += grp_b[idx] - grp_rm[idx] * sg;
    }
    ms  *= (1.0f / (float)NG);
    msh *= (1.0f / (float)NG);

    __shared__ float alpha_sh[NB];
    if (c < NB) {
        float acc = alpha_b[0];
        const float* __restrict__ pr = d_pooled + c * NC;
        #pragma unroll 8
        for (int k = 0; k < NC; k++) acc += pr[k] * alpha_w[k];
        alpha_sh[c] = 1.0f / (1.0f + expf(-acc));
    }
    __syncthreads();

    #pragma unroll 4
    for (int b = 0; b < NB; b++) {
        const float a  = alpha_sh[b];
        const float na = 1.0f - a;
        d_scale[b * NC + c] = na * gs  + a * ms;
        d_shift[b * NC + c] = na * gsh + a * msh;
    }
}

// ---------------------------------------------------------------------------
// Pass 3: pure streaming apply, 2 planes per block. Prologue = 4 scalar loads.
// ---------------------------------------------------------------------------
__global__ __launch_bounds__(TPB) void apply_kernel(const float* __restrict__ x,
                                                    float* __restrict__ out) {
    const int plane0 = blockIdx.x * 2;

    const float sc0 = d_scale[plane0],     sf0 = d_shift[plane0];
    const float sc1 = d_scale[plane0 + 1], sf1 = d_shift[plane0 + 1];

    const float4* __restrict__ xp =
        reinterpret_cast<const float4*>(x + (size_t)plane0 * NHW);
    float4* __restrict__ op =
        reinterpret_cast<float4*>(out + (size_t)plane0 * NHW);

    float4 v[PER_TH];
    #pragma unroll
    for (int k = 0; k < PER_TH; k++)
        v[k] = __ldcs(&xp[threadIdx.x + k * TPB]);   // last use of x: evict-first

    #pragma unroll
    for (int k = 0; k < PER_TH; k++) {
        const int j = threadIdx.x + k * TPB;
        const float sc = (j < NHW4) ? sc0 : sc1;
        const float sf = (j < NHW4) ? sf0 : sf1;
        float4 r;
        r.x = fmaf(v[k].x, sc, sf);
        r.y = fmaf(v[k].y, sc, sf);
        r.z = fmaf(v[k].z, sc, sf);
        r.w = fmaf(v[k].w, sc, sf);
        __stcs(&op[j], r);   // streaming store: don't pollute L2
    }
}

extern "C" void kernel_launch(void* const* d_in, const int* in_sizes, int n_in,
                              void* d_out, int out_size) {
    const float* x       = (const float*)d_in[0];
    // d_in[1] = labels (unused)
    const float* alpha_w = (const float*)d_in[2];
    const float* alpha_b = (const float*)d_in[3];
    const float* g_w     = (const float*)d_in[4];
    const float* g_b     = (const float*)d_in[5];
    const float* g_rm    = (const float*)d_in[6];
    const float* g_rv    = (const float*)d_in[7];
    const float* grp_w   = (const float*)d_in[8];
    const float* grp_b   = (const float*)d_in[9];
    const float* grp_rm  = (const float*)d_in[10];
    const float* grp_rv  = (const float*)d_in[11];
    float* out = (float*)d_out;

    pool_kernel<<<NPAIR, TPB>>>(x);
    coef_kernel<<<1, NC>>>(alpha_w, alpha_b, g_w, g_b, g_rm, g_rv,
                           grp_w, grp_b, grp_rm, grp_rv);
    apply_kernel<<<NPAIR, TPB>>>(x, out);
}

// round 4
// speedup vs baseline: 1.0023x; 1.0023x over previous
#include <cuda_runtime.h>

#define NB 32
#define NC 256
#define NHW 3136
#define NHW4 784          // float4 per plane
#define NG 32
#define EPSV 1e-5f

#define NPLANE (NB * NC)      // 8192 planes
#define SGRID  (NPLANE / 8)   // 1024 blocks, 8 warps each = 1 warp/plane

__device__ float d_pooled[NPLANE];
__device__ float d_scale[NPLANE];
__device__ float d_shift[NPLANE];

// ---------------------------------------------------------------------------
// Pass 1: mean pool. One warp per plane; 3x8 front-batched float4 loads + tail.
// No shared memory, no block sync. Single wave (1024 blocks, <=8/SM).
// ---------------------------------------------------------------------------
__global__ __launch_bounds__(256) void pool_kernel(const float* __restrict__ x) {
    const int plane = (blockIdx.x << 3) + (threadIdx.x >> 5);
    const int lane  = threadIdx.x & 31;
    const float4* __restrict__ xp =
        reinterpret_cast<const float4*>(x) + (size_t)plane * NHW4;

    float s = 0.0f;
    float4 v[8];
    #pragma unroll
    for (int b = 0; b < 3; b++) {                 // 3 batches of 8 -> 768 float4
        #pragma unroll
        for (int k = 0; k < 8; k++)
            v[k] = xp[lane + (b * 8 + k) * 32];
        #pragma unroll
        for (int k = 0; k < 8; k++)
            s += (v[k].x + v[k].y) + (v[k].z + v[k].w);
    }
    if (lane < 16) {                              // tail: 784 - 768 = 16
        float4 t = xp[768 + lane];
        s += (t.x + t.y) + (t.z + t.w);
    }

    #pragma unroll
    for (int o = 16; o > 0; o >>= 1)
        s += __shfl_down_sync(0xffffffffu, s, o);
    if (lane == 0)
        d_pooled[plane] = s * (1.0f / (float)NHW);
}

// ---------------------------------------------------------------------------
// Pass 2: per-channel coefficients + per-batch alpha + fused scale/shift.
// Single block, 256 threads (thread == channel).
// ---------------------------------------------------------------------------
__global__ void coef_kernel(const float* __restrict__ alpha_w,
                            const float* __restrict__ alpha_b,
                            const float* __restrict__ g_w,
                            const float* __restrict__ g_b,
                            const float* __restrict__ g_rm,
                            const float* __restrict__ g_rv,
                            const float* __restrict__ grp_w,
                            const float* __restrict__ grp_b,
                            const float* __restrict__ grp_rm,
                            const float* __restrict__ grp_rv) {
    const int c = threadIdx.x;   // 0..255

    const float gs  = g_w[c] * rsqrtf(g_rv[c] + EPSV);
    const float gsh = g_b[c] - g_rm[c] * gs;

    float ms = 0.0f, msh = 0.0f;
    #pragma unroll 8
    for (int g = 0; g < NG; g++) {
        const int idx = g * NC + c;
        const float sg = grp_w[idx] * rsqrtf(grp_rv[idx] + EPSV);
        ms  += sg;
        msh += grp_b[idx] - grp_rm[idx] * sg;
    }
    ms  *= (1.0f / (float)NG);
    msh *= (1.0f / (float)NG);

    __shared__ float alpha_sh[NB];
    if (c < NB) {
        float acc = alpha_b[0];
        const float* __restrict__ pr = d_pooled + c * NC;
        #pragma unroll 8
        for (int k = 0; k < NC; k++) acc += pr[k] * alpha_w[k];
        alpha_sh[c] = 1.0f / (1.0f + expf(-acc));
    }
    __syncthreads();

    #pragma unroll 4
    for (int b = 0; b < NB; b++) {
        const float a  = alpha_sh[b];
        const float na = 1.0f - a;
        d_scale[b * NC + c] = na * gs  + a * ms;
        d_shift[b * NC + c] = na * gsh + a * msh;
    }
}

// ---------------------------------------------------------------------------
// Pass 3: apply. One warp per plane, 3x8 front-batched stream, single wave.
// ---------------------------------------------------------------------------
__global__ __launch_bounds__(256) void apply_kernel(const float* __restrict__ x,
                                                    float* __restrict__ out) {
    const int plane = (blockIdx.x << 3) + (threadIdx.x >> 5);
    const int lane  = threadIdx.x & 31;

    const float sc = d_scale[plane];   // warp-uniform broadcast load
    const float sf = d_shift[plane];

    const float4* __restrict__ xp =
        reinterpret_cast<const float4*>(x) + (size_t)plane * NHW4;
    float4* __restrict__ op =
        reinterpret_cast<float4*>(out) + (size_t)plane * NHW4;

    float4 v[8];
    #pragma unroll
    for (int b = 0; b < 3; b++) {
        #pragma unroll
        for (int k = 0; k < 8; k++)
            v[k] = __ldcs(&xp[lane + (b * 8 + k) * 32]);
        #pragma unroll
        for (int k = 0; k < 8; k++) {
            float4 r;
            r.x = fmaf(v[k].x, sc, sf);
            r.y = fmaf(v[k].y, sc, sf);
            r.z = fmaf(v[k].z, sc, sf);
            r.w = fmaf(v[k].w, sc, sf);
            __stcs(&op[lane + (b * 8 + k) * 32], r);
        }
    }
    if (lane < 16) {
        float4 t = __ldcs(&xp[768 + lane]);
        float4 r;
        r.x = fmaf(t.x, sc, sf);
        r.y = fmaf(t.y, sc, sf);
        r.z = fmaf(t.z, sc, sf);
        r.w = fmaf(t.w, sc, sf);
        __stcs(&op[768 + lane], r);
    }
}

extern "C" void kernel_launch(void* const* d_in, const int* in_sizes, int n_in,
                              void* d_out, int out_size) {
    const float* x       = (const float*)d_in[0];
    // d_in[1] = labels (unused)
    const float* alpha_w = (const float*)d_in[2];
    const float* alpha_b = (const float*)d_in[3];
    const float* g_w     = (const float*)d_in[4];
    const float* g_b     = (const float*)d_in[5];
    const float* g_rm    = (const float*)d_in[6];
    const float* g_rv    = (const float*)d_in[7];
    const float* grp_w   = (const float*)d_in[8];
    const float* grp_b   = (const float*)d_in[9];
    const float* grp_rm  = (const float*)d_in[10];
    const float* grp_rv  = (const float*)d_in[11];
    float* out = (float*)d_out;

    pool_kernel<<<SGRID, 256>>>(x);
    coef_kernel<<<1, NC>>>(alpha_w, alpha_b, g_w, g_b, g_rm, g_rv,
                           grp_w, grp_b, grp_rm, grp_rv);
    apply_kernel<<<SGRID, 256>>>(x, out);
}